// round 16
// baseline (speedup 1.0000x reference)
#include <cuda_runtime.h>
#include <cuda_fp16.h>
#include <cstdint>

#define Kk 8
#define Dd 768
#define Gg 20000
#define TOPKN 200
#define BP 256
#define NROW 2048
#define KD 6144
#define SCALE 0.03608439182435161f

// screen GEMM tiling: BM=128 x BN=160 (125*160 = 20000 exactly), 256 threads
#define BM 128
#define BN 160
#define NTILE_N 125
#define NCHUNK 192          // KD/32
#define OFF_BHS 8192
#define STG_S 18432
#define SMEM_SCREEN (2 * STG_S)

#define KMAX 1024
#define MARGIN 0.012f

__device__ float g_w[Kk];
__device__ float g_cb[BP];
__device__ float g_bqbk;
__device__ float g_r[Dd];
__device__ float g_v[Dd];
__device__ float g_M[Dd * Dd];
__device__ float g_Q2[NROW * Dd];
__device__ __half g_Ah[NROW * Dd];       // f16 hi-split of Q2 (written by gemm_Q2)
__device__ float g_qb[NROW];
__device__ float g_rowbias[BP];
__device__ float g_impact[BP * Gg];      // screen values
__device__ int   g_cand[BP * KMAX];
__device__ int   g_ncand[BP];
__device__ float g_exval[BP * KMAX];
// gene-major rescore machinery
__device__ int   g_gcnt[Gg];
__device__ int   g_goff[Gg];
__device__ int   g_pairs[BP * KMAX];
__device__ int   g_npairs;

// ---------------- helpers ----------------
__device__ __forceinline__ uint32_t smem_u32(const void* p) {
    uint32_t a;
    asm("{ .reg .u64 t; cvta.to.shared.u64 t, %1; cvt.u32.u64 %0, t; }" : "=r"(a) : "l"(p));
    return a;
}
__device__ __forceinline__ void ldsm4(uint32_t* r, uint32_t a) {
    asm volatile("ldmatrix.sync.aligned.m8n8.x4.shared.b16 {%0,%1,%2,%3}, [%4];"
                 : "=r"(r[0]), "=r"(r[1]), "=r"(r[2]), "=r"(r[3]) : "r"(a));
}
__device__ __forceinline__ void mma16816(float* c, const uint32_t* a, const uint32_t* b) {
    asm volatile("mma.sync.aligned.m16n8k16.row.col.f32.f16.f16.f32 "
                 "{%0,%1,%2,%3}, {%4,%5,%6,%7}, {%8,%9}, {%0,%1,%2,%3};"
                 : "+f"(c[0]), "+f"(c[1]), "+f"(c[2]), "+f"(c[3])
                 : "r"(a[0]), "r"(a[1]), "r"(a[2]), "r"(a[3]), "r"(b[0]), "r"(b[1]));
}
__device__ __forceinline__ void cvt_sts_hi(float4 f, uint32_t addr) {
    __half2 h01 = __floats2half2_rn(f.x, f.y);
    __half2 h23 = __floats2half2_rn(f.z, f.w);
    uint32_t h0 = *(uint32_t*)&h01, h1 = *(uint32_t*)&h23;
    asm volatile("st.shared.v2.b32 [%0], {%1,%2};" :: "r"(addr), "r"(h0), "r"(h1) : "memory");
}
__device__ __forceinline__ void sts_u2(uint2 v, uint32_t addr) {
    asm volatile("st.shared.v2.b32 [%0], {%1,%2};" :: "r"(addr), "r"(v.x), "r"(v.y) : "memory");
}
__device__ __forceinline__ unsigned int fkey(float v) {
    unsigned int u = __float_as_uint(v);
    return (u & 0x80000000u) ? ~u : (u | 0x80000000u);
}
__device__ __forceinline__ float fkey_inv(unsigned int k) {
    return (k & 0x80000000u) ? __uint_as_float(k ^ 0x80000000u) : __uint_as_float(~k);
}

// ---- merged prep + rv + zero of gene counters ----
// blocks 0..11: rv; block 12: softmax/conf_bias/bq.bk; blocks 13..92: zero g_gcnt
__global__ void preprv_kernel(const float* __restrict__ conf, const float* __restrict__ fw,
                              const float* __restrict__ bq, const float* __restrict__ bk,
                              const float* __restrict__ Wq, const float* __restrict__ Wk,
                              float* __restrict__ out_w, int write_w) {
    int t = threadIdx.x;
    if (blockIdx.x >= 13) {
        int idx = (blockIdx.x - 13) * 256 + t;
        if (idx < Gg) g_gcnt[idx] = 0;
        return;
    }
    if (blockIdx.x < 12) {
        if (t < 128) {
            int idx = blockIdx.x * 128 + t;
            if (idx < Dd) {
                float s = 0.f;
                for (int e = 0; e < Dd; e++) s += bq[e] * Wk[e * Dd + idx];
                g_r[idx] = s;
            } else {
                int c = idx - Dd;
                float s = 0.f;
                for (int e = 0; e < Dd; e++) s += Wq[e * Dd + c] * bk[e];
                g_v[c] = s;
            }
        }
        return;
    }
    __shared__ float sw[Kk];
    __shared__ float red[256];
    if (t == 0) {
        float mx = fw[0];
        for (int k = 1; k < Kk; k++) mx = fmaxf(mx, fw[k]);
        float e[Kk]; float s = 0.f;
        for (int k = 0; k < Kk; k++) { e[k] = expf(fw[k] - mx); s += e[k]; }
        for (int k = 0; k < Kk; k++) { sw[k] = e[k] / s; g_w[k] = sw[k]; }
    }
    __syncthreads();
    float p = 0.f;
    for (int i = t; i < Dd; i += 256) p += bq[i] * bk[i];
    red[t] = p; __syncthreads();
    for (int o = 128; o > 0; o >>= 1) { if (t < o) red[t] += red[t + o]; __syncthreads(); }
    if (t == 0) g_bqbk = red[0];
    float cb = 0.f;
    for (int k = 0; k < Kk; k++) {
        float c = fmaxf(conf[t * Kk + k], 1e-6f);
        cb += logf(c) * sw[k];
    }
    g_cb[t] = cb;
    if (write_w && t < Kk) out_w[t] = sw[t];
}

// ---- M = Wq^T @ Wk ----
__global__ void __launch_bounds__(256) gemm_M_kernel(const float* __restrict__ Wq,
                                                     const float* __restrict__ Wk) {
    __shared__ float As[16][64];
    __shared__ float Bs[16][64];
    int t = threadIdx.x;
    int d0 = blockIdx.x * 64, c0 = blockIdx.y * 64;
    int tx = t & 15, ty = t >> 4;
    float hi[4][4];
    #pragma unroll
    for (int i = 0; i < 4; i++)
        #pragma unroll
        for (int j = 0; j < 4; j++) hi[i][j] = 0.f;
    int lkk = (t * 4) >> 6, lm = (t * 4) & 63;
    for (int e0 = 0; e0 < Dd; e0 += 16) {
        float4 a = *(const float4*)(Wq + (e0 + lkk) * Dd + c0 + lm);
        float4 b = *(const float4*)(Wk + (e0 + lkk) * Dd + d0 + lm);
        __syncthreads();
        *(float4*)&As[lkk][lm] = a;
        *(float4*)&Bs[lkk][lm] = b;
        __syncthreads();
        float tv[4][4];
        #pragma unroll
        for (int i = 0; i < 4; i++)
            #pragma unroll
            for (int j = 0; j < 4; j++) tv[i][j] = 0.f;
        #pragma unroll
        for (int kk = 0; kk < 16; kk++) {
            float4 av = *(const float4*)&As[kk][ty * 4];
            float4 bv = *(const float4*)&Bs[kk][tx * 4];
            float am[4] = {av.x, av.y, av.z, av.w};
            float bn[4] = {bv.x, bv.y, bv.z, bv.w};
            #pragma unroll
            for (int i = 0; i < 4; i++)
                #pragma unroll
                for (int j = 0; j < 4; j++) tv[i][j] = fmaf(am[i], bn[j], tv[i][j]);
        }
        #pragma unroll
        for (int i = 0; i < 4; i++)
            #pragma unroll
            for (int j = 0; j < 4; j++) hi[i][j] += tv[i][j];
    }
    #pragma unroll
    for (int i = 0; i < 4; i++)
        #pragma unroll
        for (int j = 0; j < 4; j++)
            g_M[(c0 + ty * 4 + i) * Dd + d0 + tx * 4 + j] = hi[i][j];
}

// ---- Q2 = w_k * (ctxQ @ M + r); also writes f16 hi-split for the screen ----
__global__ void __launch_bounds__(256) gemm_Q2_kernel(const float* __restrict__ ctxQ) {
    __shared__ float As[16][68];
    __shared__ float Bs[16][64];
    int t = threadIdx.x;
    int d0 = blockIdx.x * 64, m0 = blockIdx.y * 64;
    int tx = t & 15, ty = t >> 4;
    float hi[4][4];
    #pragma unroll
    for (int i = 0; i < 4; i++)
        #pragma unroll
        for (int j = 0; j < 4; j++) hi[i][j] = 0.f;
    int alm = (t * 4) >> 4;
    int akk = (t * 4) & 15;
    int bkk = (t * 4) >> 6, bn = (t * 4) & 63;
    for (int e0 = 0; e0 < Dd; e0 += 16) {
        float4 a = *(const float4*)(ctxQ + (m0 + alm) * Dd + e0 + akk);
        float4 b = *(const float4*)(g_M + (e0 + bkk) * Dd + d0 + bn);
        __syncthreads();
        As[akk + 0][alm] = a.x; As[akk + 1][alm] = a.y;
        As[akk + 2][alm] = a.z; As[akk + 3][alm] = a.w;
        *(float4*)&Bs[bkk][bn] = b;
        __syncthreads();
        float tv[4][4];
        #pragma unroll
        for (int i = 0; i < 4; i++)
            #pragma unroll
            for (int j = 0; j < 4; j++) tv[i][j] = 0.f;
        #pragma unroll
        for (int kk = 0; kk < 16; kk++) {
            float4 av = *(const float4*)&As[kk][ty * 4];
            float4 bv = *(const float4*)&Bs[kk][tx * 4];
            float am[4] = {av.x, av.y, av.z, av.w};
            float bn2[4] = {bv.x, bv.y, bv.z, bv.w};
            #pragma unroll
            for (int i = 0; i < 4; i++)
                #pragma unroll
                for (int j = 0; j < 4; j++) tv[i][j] = fmaf(am[i], bn2[j], tv[i][j]);
        }
        #pragma unroll
        for (int i = 0; i < 4; i++)
            #pragma unroll
            for (int j = 0; j < 4; j++) hi[i][j] += tv[i][j];
    }
    #pragma unroll
    for (int i = 0; i < 4; i++) {
        int m = m0 + ty * 4 + i;
        float wk = g_w[m & 7];
        #pragma unroll
        for (int j = 0; j < 4; j++) {
            int d = d0 + tx * 4 + j;
            float v = wk * (hi[i][j] + g_r[d]);
            g_Q2[m * Dd + d] = v;
            g_Ah[m * Dd + d] = __float2half_rn(v);
        }
    }
}

__global__ void qb_kernel(const float* __restrict__ ctxQ) {
    int w = (blockIdx.x * blockDim.x + threadIdx.x) >> 5;
    int lane = threadIdx.x & 31;
    if (w >= NROW) return;
    const float* rowp = ctxQ + w * Dd;
    float s = 0.f;
    for (int c = lane; c < Dd; c += 32) s += rowp[c] * g_v[c];
    #pragma unroll
    for (int o = 16; o > 0; o >>= 1) s += __shfl_xor_sync(0xFFFFFFFFu, s, o);
    if (lane == 0) g_qb[w] = g_w[w & 7] * (s + g_bqbk);
}

__global__ void rowbias_kernel() {
    int t = threadIdx.x;
    if (t < BP) {
        float s = 0.f;
        for (int k = 0; k < Kk; k++) s += g_qb[t * Kk + k];
        g_rowbias[t] = g_cb[t] + SCALE * s;
    }
}

// ---- screen GEMM (unchanged from R15) ----
__global__ void __launch_bounds__(256, 1) screen_gemm(const float* __restrict__ Bg) {
    extern __shared__ char smem[];
    uint32_t sb = smem_u32(smem);
    int t = threadIdx.x, lane = t & 31, wid = t >> 5;
    int wr = wid & 3, wc = wid >> 2;
    int m0 = blockIdx.x * BM, n0 = blockIdx.y * BN;

    uint32_t offA[2][2], offB[5][2];
    #pragma unroll
    for (int mt = 0; mt < 2; mt++)
        #pragma unroll
        for (int ks = 0; ks < 2; ks++) {
            int r = wr * 32 + mt * 16 + (lane & 15);
            int u = ks * 2 + (lane >> 4);
            offA[mt][ks] = r * 64 + ((u ^ ((r >> 1) & 3)) << 4);
        }
    #pragma unroll
    for (int ng = 0; ng < 5; ng++)
        #pragma unroll
        for (int ks = 0; ks < 2; ks++) {
            int r = wc * 80 + ng * 16 + (lane & 7) + ((lane >> 4) << 3);
            int u = ks * 2 + ((lane >> 3) & 1);
            offB[ng][ks] = r * 64 + ((u ^ ((r >> 1) & 3)) << 4);
        }

    float C[2][10][4];
    #pragma unroll
    for (int i = 0; i < 2; i++)
        #pragma unroll
        for (int j = 0; j < 10; j++)
            #pragma unroll
            for (int q = 0; q < 4; q++) C[i][j][q] = 0.f;

    int arow = t >> 1, akh = t & 1;
    int brow2 = 128 + (t >> 1);
    bool has2 = (t < 64);
    const __half* pA = g_Ah + (size_t)(m0 / BM) * (BM * KD) + (size_t)arow * KD + akh * 16;
    const float* pB = Bg + (size_t)(n0 + arow) * KD + akh * 16;
    const float* pB2 = Bg + (size_t)(n0 + (has2 ? brow2 : 128)) * KD + akh * 16;
    uint32_t stA[4], stB2[4];
    #pragma unroll
    for (int i = 0; i < 4; i++) {
        int klo = akh * 16 + i * 4;
        stA[i] = (uint32_t)arow * 64 + (((klo >> 3) ^ ((arow >> 1) & 3)) << 4) + (klo & 7) * 2;
        stB2[i] = (uint32_t)brow2 * 64 + (((klo >> 3) ^ ((brow2 >> 1) & 3)) << 4) + (klo & 7) * 2;
    }

    uint2 pvA[4];
    float4 pvB[4], pvB2[4];
#define SLOADC(s) { \
    _Pragma("unroll") \
    for (int i = 0; i < 4; i++) { \
        pvA[i] = *(const uint2*)(pA + (s) * 32 + i * 4); \
        pvB[i] = *(const float4*)(pB + (s) * 32 + i * 4); \
        if (has2) pvB2[i] = *(const float4*)(pB2 + (s) * 32 + i * 4); \
    } }
#define SCVTST(stg) { \
    uint32_t base_ = sb + (stg) * STG_S; \
    _Pragma("unroll") \
    for (int i = 0; i < 4; i++) { \
        sts_u2(pvA[i], base_ + stA[i]); \
        cvt_sts_hi(pvB[i], base_ + OFF_BHS + stA[i]); \
    } \
    if (has2) { \
        _Pragma("unroll") \
        for (int i = 0; i < 4; i++) \
            cvt_sts_hi(pvB2[i], base_ + OFF_BHS + stB2[i]); \
    } }

    SLOADC(0);
    SCVTST(0);
    SLOADC(1);
    __syncthreads();

    #pragma unroll 1
    for (int s = 0; s < NCHUNK; s++) {
        int cur = s & 1;
        uint32_t base = sb + cur * STG_S;
        uint32_t ah0[2][4], bh0[10][2];
        #pragma unroll
        for (int mt = 0; mt < 2; mt++) ldsm4(ah0[mt], base + offA[mt][0]);
        #pragma unroll
        for (int ng = 0; ng < 5; ng++) {
            uint32_t rr[4];
            ldsm4(rr, base + OFF_BHS + offB[ng][0]);
            bh0[2 * ng][0] = rr[0]; bh0[2 * ng][1] = rr[1];
            bh0[2 * ng + 1][0] = rr[2]; bh0[2 * ng + 1][1] = rr[3];
        }
        if (s < NCHUNK - 1) {
            SCVTST(1 - cur);
            if (s < NCHUNK - 2) SLOADC(s + 2);
        }
        #pragma unroll
        for (int nt = 0; nt < 10; nt++)
            #pragma unroll
            for (int mt = 0; mt < 2; mt++) mma16816(C[mt][nt], ah0[mt], bh0[nt]);
        {
            uint32_t ah1[2][4], bh1[10][2];
            #pragma unroll
            for (int mt = 0; mt < 2; mt++) ldsm4(ah1[mt], base + offA[mt][1]);
            #pragma unroll
            for (int ng = 0; ng < 5; ng++) {
                uint32_t rr[4];
                ldsm4(rr, base + OFF_BHS + offB[ng][1]);
                bh1[2 * ng][0] = rr[0]; bh1[2 * ng][1] = rr[1];
                bh1[2 * ng + 1][0] = rr[2]; bh1[2 * ng + 1][1] = rr[3];
            }
            #pragma unroll
            for (int nt = 0; nt < 10; nt++)
                #pragma unroll
                for (int mt = 0; mt < 2; mt++) mma16816(C[mt][nt], ah1[mt], bh1[nt]);
        }
        __syncthreads();
    }

    int gid = lane >> 2, tig = lane & 3;
    #pragma unroll
    for (int mt = 0; mt < 2; mt++) {
        int mA = m0 + wr * 32 + mt * 16 + gid;
        float rbA = g_rowbias[mA];
        float rbB = g_rowbias[mA + 8];
        #pragma unroll
        for (int nt = 0; nt < 10; nt++) {
            int n = n0 + wc * 80 + nt * 8 + tig * 2;
            float2 v0 = make_float2(SCALE * C[mt][nt][0] + rbA, SCALE * C[mt][nt][1] + rbA);
            float2 v1 = make_float2(SCALE * C[mt][nt][2] + rbB, SCALE * C[mt][nt][3] + rbB);
            *(float2*)(g_impact + (size_t)mA * Gg + n) = v0;
            *(float2*)(g_impact + (size_t)(mA + 8) * Gg + n) = v1;
        }
    }
}

// ---- select: radix rank-200, gather candidates >= T - MARGIN, count per gene ----
__global__ void select_kernel() {
    int row = blockIdx.x, t = threadIdx.x;
    const float* vals = g_impact + (size_t)row * Gg;
    __shared__ unsigned int hist[256];
    __shared__ unsigned int sh_prefix;
    __shared__ int sh_r;
    __shared__ int cnt;
    if (t == 0) { sh_prefix = 0u; sh_r = TOPKN; cnt = 0; }
    __syncthreads();
    for (int pass = 3; pass >= 0; pass--) {
        hist[t] = 0u;
        __syncthreads();
        unsigned int pmask = (pass == 3) ? 0u : (0xFFFFFFFFu << ((pass + 1) * 8));
        unsigned int prefix = sh_prefix;
        for (int g = t; g < Gg; g += 256) {
            unsigned int key = fkey(vals[g]);
            if ((key & pmask) == prefix) atomicAdd(&hist[(key >> (pass * 8)) & 0xFF], 1u);
        }
        __syncthreads();
        if (t == 0) {
            int r = sh_r;
            for (int b = 255; b >= 0; b--) {
                int h = (int)hist[b];
                if (r > h) r -= h;
                else { sh_prefix = prefix | ((unsigned int)b << (pass * 8)); sh_r = r; break; }
            }
        }
        __syncthreads();
    }
    float thresh = fkey_inv(sh_prefix) - MARGIN;
    for (int g = t; g < Gg; g += 256) {
        if (vals[g] >= thresh) {
            int pos = atomicAdd(&cnt, 1);
            if (pos < KMAX) {
                g_cand[row * KMAX + pos] = g;
                atomicAdd(&g_gcnt[g], 1);
            }
        }
    }
    __syncthreads();
    if (t == 0) g_ncand[row] = cnt < KMAX ? cnt : KMAX;
}

// ---- scan: exclusive prefix over g_gcnt -> g_goff; total -> g_npairs ----
__global__ void scan_kernel() {
    __shared__ int psum[256];
    int t = threadIdx.x;
    const int CH = 80;                     // 256*80 = 20480 >= Gg
    int lo = t * CH, hi = lo + CH < Gg ? lo + CH : Gg;
    int s = 0;
    for (int g = lo; g < hi; g++) s += g_gcnt[g];
    psum[t] = s;
    __syncthreads();
    for (int off = 1; off < 256; off <<= 1) {
        int u = (t >= off) ? psum[t - off] : 0;
        __syncthreads();
        psum[t] += u;
        __syncthreads();
    }
    int run = psum[t] - s;                 // exclusive base for this thread's range
    for (int g = lo; g < hi; g++) { int c = g_gcnt[g]; g_goff[g] = run; run += c; }
    if (t == 255) g_npairs = psum[255];
}

// ---- scatter: pairs sorted by gene (counting sort); g_goff used as cursor ----
__global__ void scatter_kernel() {
    int row = blockIdx.x, t = threadIdx.x;
    int nc = g_ncand[row];
    for (int i = t; i < nc; i += 256) {
        int g = g_cand[row * KMAX + i];
        int pos = atomicAdd(&g_goff[g], 1);
        g_pairs[pos] = row * KMAX + i;
    }
}

// ---- gene-major exact rescore: warp per pair; adjacent warps share B rows (L2).
// Same per-lane fma/shuffle order as before -> bit-identical values.
__global__ void __launch_bounds__(256) rescore2_kernel(const float* __restrict__ Bg) {
    int wid = threadIdx.x >> 5, lane = threadIdx.x & 31;
    int w = blockIdx.x * 8 + wid;
    int n = g_npairs;
    int stride = gridDim.x * 8;
    for (int p = w; p < n; p += stride) {
        int enc = g_pairs[p];
        int row = enc >> 10;               // KMAX = 1024
        int g = g_cand[enc];
        const float4* b4 = (const float4*)(Bg + (size_t)g * KD);
        const float4* q4 = (const float4*)(g_Q2 + (size_t)row * KD);
        float acc = 0.f;
        for (int i = lane; i < KD / 4; i += 32) {
            float4 bb = b4[i];
            float4 qq = q4[i];
            acc = fmaf(qq.x, bb.x, acc);
            acc = fmaf(qq.y, bb.y, acc);
            acc = fmaf(qq.z, bb.z, acc);
            acc = fmaf(qq.w, bb.w, acc);
        }
        #pragma unroll
        for (int o = 16; o > 0; o >>= 1) acc += __shfl_xor_sync(0xFFFFFFFFu, acc, o);
        if (lane == 0) g_exval[enc] = SCALE * acc + g_rowbias[row];
    }
}

// ---- final: rank candidates by exact value, zero-fill, scatter top-200 ----
__global__ void final_kernel(float* __restrict__ out) {
    __shared__ int sidx[KMAX];
    __shared__ unsigned int skey[KMAX];
    __shared__ float sval[KMAX];
    int row = blockIdx.x, t = threadIdx.x;
    int nc = g_ncand[row];
    for (int i = t; i < nc; i += 256) {
        sidx[i] = g_cand[row * KMAX + i];
        float v = g_exval[row * KMAX + i];
        sval[i] = v;
        skey[i] = fkey(v);
    }
    float* orow = out + (size_t)row * Gg;
    for (int g = t; g < Gg; g += 256) orow[g] = 0.f;
    __syncthreads();
    for (int i = t; i < nc; i += 256) {
        unsigned int ki = skey[i]; int xi = sidx[i];
        int rank = 0;
        for (int j = 0; j < nc; j++) {
            unsigned int kj = skey[j];
            if (kj > ki || (kj == ki && sidx[j] < xi)) rank++;
        }
        if (rank < TOPKN) orow[xi] = sval[i];
    }
}

extern "C" void kernel_launch(void* const* d_in, const int* in_sizes, int n_in,
                              void* d_out, int out_size) {
    const float* ctxQ   = (const float*)d_in[0];
    const float* genome = (const float*)d_in[1];
    const float* conf   = (const float*)d_in[2];
    const float* Wq     = (const float*)d_in[3];
    const float* bq     = (const float*)d_in[4];
    const float* Wk     = (const float*)d_in[5];
    const float* bk     = (const float*)d_in[6];
    const float* fw     = (const float*)d_in[7];
    float* out = (float*)d_out;

    int write_w = (out_size >= BP * Gg + Kk) ? 1 : 0;

    preprv_kernel<<<93, 256>>>(conf, fw, bq, bk, Wq, Wk, out + (size_t)BP * Gg, write_w);
    gemm_M_kernel<<<dim3(12, 12), 256>>>(Wq, Wk);
    gemm_Q2_kernel<<<dim3(12, 32), 256>>>(ctxQ);
    qb_kernel<<<256, 256>>>(ctxQ);
    rowbias_kernel<<<1, 256>>>();
    screen_gemm<<<dim3(2, NTILE_N), 256, SMEM_SCREEN>>>(genome);
    select_kernel<<<256, 256>>>();
    scan_kernel<<<1, 256>>>();
    scatter_kernel<<<256, 256>>>();
    rescore2_kernel<<<296, 256>>>(genome);
    final_kernel<<<256, 256>>>(out);
}

// round 17
// speedup vs baseline: 1.6212x; 1.6212x over previous
#include <cuda_runtime.h>
#include <cuda_fp16.h>
#include <cstdint>

#define Kk 8
#define Dd 768
#define Gg 20000
#define TOPKN 200
#define BP 256
#define NROW 2048
#define KD 6144
#define SCALE 0.03608439182435161f

// screen GEMM tiling: BM=128 x BN=160 (125*160 = 20000 exactly), 256 threads
// 64-k chunks (96 of them): chunk MMA work 2560 cyc absorbs the fixed chain.
#define BM 128
#define BN 160
#define NTILE_N 125
#define NCH2 96             // KD/64
#define OFF_B2 16384        // A: 128 rows x 128B = 16KB, then B: 160 x 128B = 20KB
#define STG2 36864
#define SMEM_SCREEN (2 * STG2)

#define KMAX 1024
#define MARGIN 0.012f

__device__ float g_w[Kk];
__device__ float g_cb[BP];
__device__ float g_bqbk;
__device__ float g_r[Dd];
__device__ float g_v[Dd];
__device__ float g_M[Dd * Dd];
__device__ float g_Q2[NROW * Dd];
__device__ __half g_Ah[NROW * Dd];       // f16 hi-split of Q2 (written by gemm_Q2)
__device__ float g_qb[NROW];
__device__ float g_rowbias[BP];
__device__ float g_impact[BP * Gg];      // screen values
__device__ int   g_cand[BP * KMAX];
__device__ int   g_ncand[BP];
__device__ float g_exval[BP * KMAX];

// ---------------- helpers ----------------
__device__ __forceinline__ uint32_t smem_u32(const void* p) {
    uint32_t a;
    asm("{ .reg .u64 t; cvta.to.shared.u64 t, %1; cvt.u32.u64 %0, t; }" : "=r"(a) : "l"(p));
    return a;
}
__device__ __forceinline__ void ldsm4(uint32_t* r, uint32_t a) {
    asm volatile("ldmatrix.sync.aligned.m8n8.x4.shared.b16 {%0,%1,%2,%3}, [%4];"
                 : "=r"(r[0]), "=r"(r[1]), "=r"(r[2]), "=r"(r[3]) : "r"(a));
}
__device__ __forceinline__ void mma16816(float* c, const uint32_t* a, const uint32_t* b) {
    asm volatile("mma.sync.aligned.m16n8k16.row.col.f32.f16.f16.f32 "
                 "{%0,%1,%2,%3}, {%4,%5,%6,%7}, {%8,%9}, {%0,%1,%2,%3};"
                 : "+f"(c[0]), "+f"(c[1]), "+f"(c[2]), "+f"(c[3])
                 : "r"(a[0]), "r"(a[1]), "r"(a[2]), "r"(a[3]), "r"(b[0]), "r"(b[1]));
}
__device__ __forceinline__ void cvt_sts_hi(float4 f, uint32_t addr) {
    __half2 h01 = __floats2half2_rn(f.x, f.y);
    __half2 h23 = __floats2half2_rn(f.z, f.w);
    uint32_t h0 = *(uint32_t*)&h01, h1 = *(uint32_t*)&h23;
    asm volatile("st.shared.v2.b32 [%0], {%1,%2};" :: "r"(addr), "r"(h0), "r"(h1) : "memory");
}
__device__ __forceinline__ void sts_u4(uint4 v, uint32_t addr) {
    asm volatile("st.shared.v4.b32 [%0], {%1,%2,%3,%4};"
                 :: "r"(addr), "r"(v.x), "r"(v.y), "r"(v.z), "r"(v.w) : "memory");
}
__device__ __forceinline__ unsigned int fkey(float v) {
    unsigned int u = __float_as_uint(v);
    return (u & 0x80000000u) ? ~u : (u | 0x80000000u);
}
__device__ __forceinline__ float fkey_inv(unsigned int k) {
    return (k & 0x80000000u) ? __uint_as_float(k ^ 0x80000000u) : __uint_as_float(~k);
}

// ---- merged prep + rv ----
__global__ void preprv_kernel(const float* __restrict__ conf, const float* __restrict__ fw,
                              const float* __restrict__ bq, const float* __restrict__ bk,
                              const float* __restrict__ Wq, const float* __restrict__ Wk,
                              float* __restrict__ out_w, int write_w) {
    int t = threadIdx.x;
    if (blockIdx.x < 12) {
        if (t < 128) {
            int idx = blockIdx.x * 128 + t;
            if (idx < Dd) {
                float s = 0.f;
                for (int e = 0; e < Dd; e++) s += bq[e] * Wk[e * Dd + idx];
                g_r[idx] = s;
            } else {
                int c = idx - Dd;
                float s = 0.f;
                for (int e = 0; e < Dd; e++) s += Wq[e * Dd + c] * bk[e];
                g_v[c] = s;
            }
        }
        return;
    }
    __shared__ float sw[Kk];
    __shared__ float red[256];
    if (t == 0) {
        float mx = fw[0];
        for (int k = 1; k < Kk; k++) mx = fmaxf(mx, fw[k]);
        float e[Kk]; float s = 0.f;
        for (int k = 0; k < Kk; k++) { e[k] = expf(fw[k] - mx); s += e[k]; }
        for (int k = 0; k < Kk; k++) { sw[k] = e[k] / s; g_w[k] = sw[k]; }
    }
    __syncthreads();
    float p = 0.f;
    for (int i = t; i < Dd; i += 256) p += bq[i] * bk[i];
    red[t] = p; __syncthreads();
    for (int o = 128; o > 0; o >>= 1) { if (t < o) red[t] += red[t + o]; __syncthreads(); }
    if (t == 0) g_bqbk = red[0];
    float cb = 0.f;
    for (int k = 0; k < Kk; k++) {
        float c = fmaxf(conf[t * Kk + k], 1e-6f);
        cb += logf(c) * sw[k];
    }
    g_cb[t] = cb;
    if (write_w && t < Kk) out_w[t] = sw[t];
}

// ---- M = Wq^T @ Wk ----
__global__ void __launch_bounds__(256) gemm_M_kernel(const float* __restrict__ Wq,
                                                     const float* __restrict__ Wk) {
    __shared__ float As[16][64];
    __shared__ float Bs[16][64];
    int t = threadIdx.x;
    int d0 = blockIdx.x * 64, c0 = blockIdx.y * 64;
    int tx = t & 15, ty = t >> 4;
    float hi[4][4];
    #pragma unroll
    for (int i = 0; i < 4; i++)
        #pragma unroll
        for (int j = 0; j < 4; j++) hi[i][j] = 0.f;
    int lkk = (t * 4) >> 6, lm = (t * 4) & 63;
    for (int e0 = 0; e0 < Dd; e0 += 16) {
        float4 a = *(const float4*)(Wq + (e0 + lkk) * Dd + c0 + lm);
        float4 b = *(const float4*)(Wk + (e0 + lkk) * Dd + d0 + lm);
        __syncthreads();
        *(float4*)&As[lkk][lm] = a;
        *(float4*)&Bs[lkk][lm] = b;
        __syncthreads();
        float tv[4][4];
        #pragma unroll
        for (int i = 0; i < 4; i++)
            #pragma unroll
            for (int j = 0; j < 4; j++) tv[i][j] = 0.f;
        #pragma unroll
        for (int kk = 0; kk < 16; kk++) {
            float4 av = *(const float4*)&As[kk][ty * 4];
            float4 bv = *(const float4*)&Bs[kk][tx * 4];
            float am[4] = {av.x, av.y, av.z, av.w};
            float bn[4] = {bv.x, bv.y, bv.z, bv.w};
            #pragma unroll
            for (int i = 0; i < 4; i++)
                #pragma unroll
                for (int j = 0; j < 4; j++) tv[i][j] = fmaf(am[i], bn[j], tv[i][j]);
        }
        #pragma unroll
        for (int i = 0; i < 4; i++)
            #pragma unroll
            for (int j = 0; j < 4; j++) hi[i][j] += tv[i][j];
    }
    #pragma unroll
    for (int i = 0; i < 4; i++)
        #pragma unroll
        for (int j = 0; j < 4; j++)
            g_M[(c0 + ty * 4 + i) * Dd + d0 + tx * 4 + j] = hi[i][j];
}

// ---- Q2 = w_k * (ctxQ @ M + r); also writes f16 hi-split for the screen ----
__global__ void __launch_bounds__(256) gemm_Q2_kernel(const float* __restrict__ ctxQ) {
    __shared__ float As[16][68];
    __shared__ float Bs[16][64];
    int t = threadIdx.x;
    int d0 = blockIdx.x * 64, m0 = blockIdx.y * 64;
    int tx = t & 15, ty = t >> 4;
    float hi[4][4];
    #pragma unroll
    for (int i = 0; i < 4; i++)
        #pragma unroll
        for (int j = 0; j < 4; j++) hi[i][j] = 0.f;
    int alm = (t * 4) >> 4;
    int akk = (t * 4) & 15;
    int bkk = (t * 4) >> 6, bn = (t * 4) & 63;
    for (int e0 = 0; e0 < Dd; e0 += 16) {
        float4 a = *(const float4*)(ctxQ + (m0 + alm) * Dd + e0 + akk);
        float4 b = *(const float4*)(g_M + (e0 + bkk) * Dd + d0 + bn);
        __syncthreads();
        As[akk + 0][alm] = a.x; As[akk + 1][alm] = a.y;
        As[akk + 2][alm] = a.z; As[akk + 3][alm] = a.w;
        *(float4*)&Bs[bkk][bn] = b;
        __syncthreads();
        float tv[4][4];
        #pragma unroll
        for (int i = 0; i < 4; i++)
            #pragma unroll
            for (int j = 0; j < 4; j++) tv[i][j] = 0.f;
        #pragma unroll
        for (int kk = 0; kk < 16; kk++) {
            float4 av = *(const float4*)&As[kk][ty * 4];
            float4 bv = *(const float4*)&Bs[kk][tx * 4];
            float am[4] = {av.x, av.y, av.z, av.w};
            float bn2[4] = {bv.x, bv.y, bv.z, bv.w};
            #pragma unroll
            for (int i = 0; i < 4; i++)
                #pragma unroll
                for (int j = 0; j < 4; j++) tv[i][j] = fmaf(am[i], bn2[j], tv[i][j]);
        }
        #pragma unroll
        for (int i = 0; i < 4; i++)
            #pragma unroll
            for (int j = 0; j < 4; j++) hi[i][j] += tv[i][j];
    }
    #pragma unroll
    for (int i = 0; i < 4; i++) {
        int m = m0 + ty * 4 + i;
        float wk = g_w[m & 7];
        #pragma unroll
        for (int j = 0; j < 4; j++) {
            int d = d0 + tx * 4 + j;
            float v = wk * (hi[i][j] + g_r[d]);
            g_Q2[m * Dd + d] = v;
            g_Ah[m * Dd + d] = __float2half_rn(v);
        }
    }
}

__global__ void qb_kernel(const float* __restrict__ ctxQ) {
    int w = (blockIdx.x * blockDim.x + threadIdx.x) >> 5;
    int lane = threadIdx.x & 31;
    if (w >= NROW) return;
    const float* rowp = ctxQ + w * Dd;
    float s = 0.f;
    for (int c = lane; c < Dd; c += 32) s += rowp[c] * g_v[c];
    #pragma unroll
    for (int o = 16; o > 0; o >>= 1) s += __shfl_xor_sync(0xFFFFFFFFu, s, o);
    if (lane == 0) g_qb[w] = g_w[w & 7] * (s + g_bqbk);
}

__global__ void rowbias_kernel() {
    int t = threadIdx.x;
    if (t < BP) {
        float s = 0.f;
        for (int k = 0; k < Kk; k++) s += g_qb[t * Kk + k];
        g_rowbias[t] = g_cb[t] + SCALE * s;
    }
}

// ---- screen GEMM: hh product only, 64-k chunks, 128B swizzled rows ----
// Per-(m,n) k16-block accumulation order (4s+ks ascending) identical to R15
// (2s+ks ascending) -> bit-identical screen values.
__global__ void __launch_bounds__(256, 1) screen_gemm(const float* __restrict__ Bg) {
    extern __shared__ char smem[];
    uint32_t sb = smem_u32(smem);
    int t = threadIdx.x, lane = t & 31, wid = t >> 5;
    int wr = wid & 3, wc = wid >> 2;      // warp tile: 32 m x 80 n
    int m0 = blockIdx.x * BM, n0 = blockIdx.y * BN;

    // ldmatrix bases; ks applied as XOR with (ks<<5) (seg bits 1-2 = addr bits 5-6)
    uint32_t offA[2], offB[5];
    #pragma unroll
    for (int mt = 0; mt < 2; mt++) {
        int r = wr * 32 + mt * 16 + (lane & 15);
        int v0 = (lane >> 4) ^ (r & 7);
        offA[mt] = (uint32_t)r * 128 + (v0 << 4);
    }
    #pragma unroll
    for (int ng = 0; ng < 5; ng++) {
        int r = wc * 80 + ng * 16 + (lane & 7) + ((lane >> 4) << 3);
        int v0 = ((lane >> 3) & 1) ^ (r & 7);
        offB[ng] = OFF_B2 + (uint32_t)r * 128 + (v0 << 4);
    }

    float C[2][10][4];
    #pragma unroll
    for (int i = 0; i < 2; i++)
        #pragma unroll
        for (int j = 0; j < 10; j++)
            #pragma unroll
            for (int q = 0; q < 4; q++) C[i][j][q] = 0.f;

    // B convert: thread handles float4-slot qi (const) of rows r0+16j, j=0..9
    int r0 = t >> 4, qi = t & 15;
    const float* pB = Bg + (size_t)(n0 + r0) * KD + qi * 4;
    uint32_t stB = OFF_B2 + (uint32_t)r0 * 128 + ((((qi >> 1) ^ (r0 & 7))) << 4) + (qi & 1) * 8;
    // A copy: thread handles 64B half 'ah_' of row 'ar'
    int ar = t >> 1, ah_ = t & 1;
    const __half* pA = g_Ah + (size_t)(m0 + ar) * KD + ah_ * 32;
    uint32_t stA = (uint32_t)ar * 128 + ((((ah_ << 2) ^ (ar & 7))) << 4);

    float4 vB[10];
    uint4 vA[4];
#define SLOADC(s) { \
    _Pragma("unroll") \
    for (int j = 0; j < 10; j++) \
        vB[j] = *(const float4*)(pB + (size_t)j * 16 * KD + (s) * 64); \
    _Pragma("unroll") \
    for (int i = 0; i < 4; i++) \
        vA[i] = *(const uint4*)(pA + (s) * 64 + i * 8); }
#define SCVTST(stg) { \
    uint32_t base_ = sb + (stg) * STG2; \
    _Pragma("unroll") \
    for (int j = 0; j < 10; j++) \
        cvt_sts_hi(vB[j], base_ + stB + j * 2048); \
    _Pragma("unroll") \
    for (int i = 0; i < 4; i++) \
        sts_u4(vA[i], base_ + (stA ^ (i << 4))); }

    SLOADC(0);
    SCVTST(0);
    SLOADC(1);
    __syncthreads();

    #pragma unroll 1
    for (int s = 0; s < NCH2; s++) {
        int cur = s & 1;
        uint32_t base = sb + cur * STG2;
        // ks = 0: LDSM
        uint32_t a0[2][4], b0[10][2];
        #pragma unroll
        for (int mt = 0; mt < 2; mt++) ldsm4(a0[mt], base + offA[mt]);
        #pragma unroll
        for (int ng = 0; ng < 5; ng++) {
            uint32_t rr[4];
            ldsm4(rr, base + offB[ng]);
            b0[2 * ng][0] = rr[0]; b0[2 * ng][1] = rr[1];
            b0[2 * ng + 1][0] = rr[2]; b0[2 * ng + 1][1] = rr[3];
        }
        // early STS + prefetch loads (drain under the long MMA phase)
        if (s < NCH2 - 1) {
            SCVTST(1 - cur);
            if (s < NCH2 - 2) SLOADC(s + 2);
        }
        #pragma unroll
        for (int nt = 0; nt < 10; nt++)
            #pragma unroll
            for (int mt = 0; mt < 2; mt++) mma16816(C[mt][nt], a0[mt], b0[nt]);
        // ks = 1..3
        #pragma unroll
        for (int ks = 1; ks < 4; ks++) {
            uint32_t a1[2][4], b1[10][2];
            uint32_t kx = (uint32_t)(ks << 5);
            #pragma unroll
            for (int mt = 0; mt < 2; mt++) ldsm4(a1[mt], base + (offA[mt] ^ kx));
            #pragma unroll
            for (int ng = 0; ng < 5; ng++) {
                uint32_t rr[4];
                ldsm4(rr, base + (offB[ng] ^ kx));
                b1[2 * ng][0] = rr[0]; b1[2 * ng][1] = rr[1];
                b1[2 * ng + 1][0] = rr[2]; b1[2 * ng + 1][1] = rr[3];
            }
            #pragma unroll
            for (int nt = 0; nt < 10; nt++)
                #pragma unroll
                for (int mt = 0; mt < 2; mt++) mma16816(C[mt][nt], a1[mt], b1[nt]);
        }
        __syncthreads();
    }

    int gid = lane >> 2, tig = lane & 3;
    #pragma unroll
    for (int mt = 0; mt < 2; mt++) {
        int mA = m0 + wr * 32 + mt * 16 + gid;
        float rbA = g_rowbias[mA];
        float rbB = g_rowbias[mA + 8];
        #pragma unroll
        for (int nt = 0; nt < 10; nt++) {
            int n = n0 + wc * 80 + nt * 8 + tig * 2;
            float2 v0 = make_float2(SCALE * C[mt][nt][0] + rbA, SCALE * C[mt][nt][1] + rbA);
            float2 v1 = make_float2(SCALE * C[mt][nt][2] + rbB, SCALE * C[mt][nt][3] + rbB);
            *(float2*)(g_impact + (size_t)mA * Gg + n) = v0;
            *(float2*)(g_impact + (size_t)(mA + 8) * Gg + n) = v1;
        }
    }
}

// ---- select: radix rank-200 on screen, gather candidates >= T - MARGIN ----
__global__ void select_kernel() {
    int row = blockIdx.x, t = threadIdx.x;
    const float* vals = g_impact + (size_t)row * Gg;
    __shared__ unsigned int hist[256];
    __shared__ unsigned int sh_prefix;
    __shared__ int sh_r;
    __shared__ int cnt;
    if (t == 0) { sh_prefix = 0u; sh_r = TOPKN; cnt = 0; }
    __syncthreads();
    for (int pass = 3; pass >= 0; pass--) {
        hist[t] = 0u;
        __syncthreads();
        unsigned int pmask = (pass == 3) ? 0u : (0xFFFFFFFFu << ((pass + 1) * 8));
        unsigned int prefix = sh_prefix;
        for (int g = t; g < Gg; g += 256) {
            unsigned int key = fkey(vals[g]);
            if ((key & pmask) == prefix) atomicAdd(&hist[(key >> (pass * 8)) & 0xFF], 1u);
        }
        __syncthreads();
        if (t == 0) {
            int r = sh_r;
            for (int b = 255; b >= 0; b--) {
                int h = (int)hist[b];
                if (r > h) r -= h;
                else { sh_prefix = prefix | ((unsigned int)b << (pass * 8)); sh_r = r; break; }
            }
        }
        __syncthreads();
    }
    float thresh = fkey_inv(sh_prefix) - MARGIN;
    for (int g = t; g < Gg; g += 256) {
        if (vals[g] >= thresh) {
            int pos = atomicAdd(&cnt, 1);
            if (pos < KMAX) g_cand[row * KMAX + pos] = g;
        }
    }
    __syncthreads();
    if (t == 0) g_ncand[row] = cnt < KMAX ? cnt : KMAX;
}

// ---- exact rescore: fp32 dot per candidate (warp-per-candidate, q in smem) ----
__global__ void __launch_bounds__(256) rescore_kernel(const float* __restrict__ Bg) {
    __shared__ float q[KD];
    int row = blockIdx.x, t = threadIdx.x, lane = t & 31, wid = t >> 5;
    const float* qrow = g_Q2 + (size_t)row * KD;
    for (int i = t; i < KD / 4; i += 256)
        *(float4*)(q + i * 4) = *(const float4*)(qrow + i * 4);
    __syncthreads();
    int nc = g_ncand[row];
    float rb = g_rowbias[row];
    for (int slot = wid; slot < nc; slot += 8) {
        int g = g_cand[row * KMAX + slot];
        const float4* b4 = (const float4*)(Bg + (size_t)g * KD);
        float acc = 0.f;
        for (int i = lane; i < KD / 4; i += 32) {
            float4 bb = b4[i];
            float4 qq = *(const float4*)(q + i * 4);
            acc = fmaf(qq.x, bb.x, acc);
            acc = fmaf(qq.y, bb.y, acc);
            acc = fmaf(qq.z, bb.z, acc);
            acc = fmaf(qq.w, bb.w, acc);
        }
        #pragma unroll
        for (int o = 16; o > 0; o >>= 1) acc += __shfl_xor_sync(0xFFFFFFFFu, acc, o);
        if (lane == 0) g_exval[row * KMAX + slot] = SCALE * acc + rb;
    }
}

// ---- final: rank candidates by exact value, zero-fill, scatter top-200 ----
__global__ void final_kernel(float* __restrict__ out) {
    __shared__ int sidx[KMAX];
    __shared__ unsigned int skey[KMAX];
    __shared__ float sval[KMAX];
    int row = blockIdx.x, t = threadIdx.x;
    int nc = g_ncand[row];
    for (int i = t; i < nc; i += 256) {
        sidx[i] = g_cand[row * KMAX + i];
        float v = g_exval[row * KMAX + i];
        sval[i] = v;
        skey[i] = fkey(v);
    }
    float* orow = out + (size_t)row * Gg;
    for (int g = t; g < Gg; g += 256) orow[g] = 0.f;
    __syncthreads();
    for (int i = t; i < nc; i += 256) {
        unsigned int ki = skey[i]; int xi = sidx[i];
        int rank = 0;
        for (int j = 0; j < nc; j++) {
            unsigned int kj = skey[j];
            if (kj > ki || (kj == ki && sidx[j] < xi)) rank++;
        }
        if (rank < TOPKN) orow[xi] = sval[i];
    }
}

extern "C" void kernel_launch(void* const* d_in, const int* in_sizes, int n_in,
                              void* d_out, int out_size) {
    const float* ctxQ   = (const float*)d_in[0];
    const float* genome = (const float*)d_in[1];
    const float* conf   = (const float*)d_in[2];
    const float* Wq     = (const float*)d_in[3];
    const float* bq     = (const float*)d_in[4];
    const float* Wk     = (const float*)d_in[5];
    const float* bk     = (const float*)d_in[6];
    const float* fw     = (const float*)d_in[7];
    float* out = (float*)d_out;

    int write_w = (out_size >= BP * Gg + Kk) ? 1 : 0;

    cudaFuncSetAttribute(screen_gemm, cudaFuncAttributeMaxDynamicSharedMemorySize, SMEM_SCREEN);

    preprv_kernel<<<13, 256>>>(conf, fw, bq, bk, Wq, Wk, out + (size_t)BP * Gg, write_w);
    gemm_M_kernel<<<dim3(12, 12), 256>>>(Wq, Wk);
    gemm_Q2_kernel<<<dim3(12, 32), 256>>>(ctxQ);
    qb_kernel<<<256, 256>>>(ctxQ);
    rowbias_kernel<<<1, 256>>>();
    screen_gemm<<<dim3(2, NTILE_N), 256, SMEM_SCREEN>>>(genome);
    select_kernel<<<256, 256>>>();
    rescore_kernel<<<256, 256>>>(genome);
    final_kernel<<<256, 256>>>(out);
}